// round 15
// baseline (speedup 1.0000x reference)
#include <cuda_runtime.h>
#include <math.h>

#define NW 14
#define QDIM 16384
#define QBATCH 1024
#define NT 1024

typedef unsigned long long ull;

// ============ compile-time GF(2) circuit algebra ============
__host__ __device__ constexpr unsigned sig(unsigned y) { return y ^ (y >> 7); }
__host__ __device__ constexpr int cpop(unsigned x) {
    int c = 0; while (x) { c += (int)(x & 1u); x >>= 1; } return c;
}

__host__ __device__ constexpr unsigned hc(unsigned x, int c, int t) {
    int pc = 13 - c, pt = 13 - t;
    return x ^ (((x >> pc) & 1u) << pt);
}
__host__ __device__ constexpr unsigned Gf(unsigned x) {
    x = hc(x, 13, 0);
    for (int w = 12; w >= 0; --w) x = hc(x, w, w + 1);
    return x;
}
__host__ __device__ constexpr unsigned Gi(unsigned x) {
    for (int w = 0; w <= 12; ++w) x = hc(x, w, w + 1);
    x = hc(x, 13, 0);
    return x;
}
__host__ __device__ constexpr unsigned colV(int L, int w) {
    unsigned e = 1u << (13 - w);
    for (int i = 0; i < L; i++) e = Gf(e);
    return e;
}
__host__ __device__ constexpr unsigned rowR(int L, int w) {
    unsigned rr = 0;
    for (int j = 0; j < 14; j++) {
        unsigned e = 1u << j;
        for (int i = 0; i < L; i++) e = Gi(e);
        rr |= ((e >> (13 - w)) & 1u) << j;
    }
    return rr;
}

__host__ __device__ constexpr int rankbits(const unsigned* v, int n) {
    unsigned rows[9] = {}; int r = 0;
    for (int i = 0; i < n; i++) {
        unsigned x = v[i];
        for (int j = 0; j < r; j++) {
            unsigned p = rows[j];
            int hb = 13;
            while (hb > 0 && !((p >> hb) & 1u)) hb--;
            if ((x >> hb) & 1u) x ^= p;
        }
        if (x) rows[r++] = x;
    }
    return r;
}

// ---- per-layer wire partition: A(4 reg + 5 lane) + B(4 reg + 1 shfl) ----
struct Part {
    int Alane[5], Areg[4], Bw[4], Bsw;   // Bw = B reg wires, Bsw = B shfl wire
    int Bqpos[4];                        // deposit positions for tid lane bits 0..3 (pass B)
    int ok;
};

__host__ __device__ constexpr Part build_part(int L) {
    Part P = {}; P.ok = 0;
    for (int w0 = 0; w0 < 14 && !P.ok; w0++)
    for (int w1 = w0 + 1; w1 < 14 && !P.ok; w1++)
    for (int w2 = w1 + 1; w2 < 14 && !P.ok; w2++)
    for (int w3 = w2 + 1; w3 < 14 && !P.ok; w3++)
    for (int w4 = w3 + 1; w4 < 14 && !P.ok; w4++) {
        const int lw[5] = {w0, w1, w2, w3, w4};
        unsigned pr[5] = {};
        bool zero = false;
        for (int i = 0; i < 5; i++) {
            pr[i] = sig(colV(L, lw[i])) & 31u;
            if (pr[i] == 0u) zero = true;
        }
        if (zero || rankbits(pr, 5) != 5) continue;
        int rem[9] = {}; int nr = 0;
        for (int w = 0; w < 14; w++) {
            bool inl = false;
            for (int i = 0; i < 5; i++) if (lw[i] == w) inl = true;
            if (!inl) rem[nr++] = w;
        }
        for (int a0 = 0; a0 < 9 && !P.ok; a0++)
        for (int a1 = a0 + 1; a1 < 9 && !P.ok; a1++)
        for (int a2 = a1 + 1; a2 < 9 && !P.ok; a2++)
        for (int a3 = a2 + 1; a3 < 9 && !P.ok; a3++) {
            int bw[5] = {}; int nb = 0;
            for (int i = 0; i < 9; i++)
                if (i != a0 && i != a1 && i != a2 && i != a3) bw[nb++] = rem[i];
            // pivots of B's 5 columns
            bool ispiv[14] = {};
            {
                unsigned red[5] = {}; int piv[5] = {}; int r = 0;
                for (int i = 0; i < 5; i++) {
                    unsigned u = colV(L, bw[i]);
                    for (int q = 0; q < r; q++)
                        if ((u >> piv[q]) & 1u) u ^= red[q];
                    int hb = 13;
                    while (hb > 0 && !((u >> hb) & 1u)) hb--;
                    piv[r] = hb; red[r] = u; ispiv[hb] = true; r++;
                }
            }
            for (int swi = 0; swi < 5 && !P.ok; swi++) {
                const unsigned s = sig(colV(L, bw[swi])) & 31u;
                if (!s) continue;
                for (int beta = 0; beta < 5 && !P.ok; beta++) {
                    if (!((s >> beta) & 1u)) continue;
                    int qpos[4] = {}; int qi = 0; bool good = true;
                    for (int q = 0; q < 5; q++) {
                        if (q == beta) continue;
                        int pos = -1;
                        if (!ispiv[q]) pos = q;
                        else if (!ispiv[q + 7]) pos = q + 7;
                        if (pos < 0) { good = false; break; }
                        qpos[qi++] = pos;
                    }
                    if (!good) continue;
                    for (int i = 0; i < 5; i++) P.Alane[i] = lw[i];
                    P.Areg[0] = rem[a0]; P.Areg[1] = rem[a1];
                    P.Areg[2] = rem[a2]; P.Areg[3] = rem[a3];
                    int idx = 0;
                    for (int i = 0; i < 5; i++)
                        if (i != swi) P.Bw[idx++] = bw[i];
                    P.Bsw = bw[swi];
                    for (int i = 0; i < 4; i++) P.Bqpos[i] = qpos[i];
                    P.ok = 1;
                }
            }
        }
    }
    return P;
}

// ---- merged pass descriptor ----
struct MPass {
    int L, K, nsh, ndep, ngrp, ok;
    unsigned vcol[9], rrow[9];
    int gate[9], zflip[9];
    unsigned rawc[8], scombo[8], v0raw, sv0;
    unsigned lanS[5], lanR[5];
    unsigned gmask[12]; int gshift[12];
    int Pmv[9];
};

__host__ __device__ constexpr MPass build_mpass(int pi) {
    MPass M = {};
    const int L = pi >> 1;
    const bool isA = (pi & 1) == 0;
    const Part T = build_part(L);
    M.ok = T.ok;
    int ws[9] = {};
    const int K = isA ? 9 : 5;
    if (isA) {
        for (int i = 0; i < 4; i++) ws[i] = T.Areg[i];
        for (int i = 0; i < 5; i++) ws[4 + i] = T.Alane[i];
    } else {
        for (int i = 0; i < 4; i++) ws[i] = T.Bw[i];
        ws[4] = T.Bsw;
    }
    M.L = L; M.K = K; M.nsh = K - 4;
    for (int j = 0; j < K; j++) {
        M.vcol[j] = colV(L, ws[j]);
        M.rrow[j] = rowR(L, ws[j]);
        M.gate[j] = L * 14 + ws[j];
    }
    M.v0raw = M.vcol[0]; M.sv0 = sig(M.vcol[0]);
    for (int m = 0; m < 8; m++) {
        unsigned cb = 0;
        for (int i = 0; i < 3; i++)
            if ((m >> i) & 1) cb ^= M.vcol[1 + i];
        M.rawc[m] = cb; M.scombo[m] = sig(cb);
    }
    for (int j = 0; j < M.nsh; j++) {
        M.lanS[j] = sig(M.vcol[4 + j]);
        M.lanR[j] = M.vcol[4 + j];
    }
    // pivots of all K columns
    bool ispiv[14] = {};
    {
        unsigned red[9] = {}; int piv[9] = {}; int r = 0;
        for (int i = 0; i < K; i++) {
            unsigned u = M.vcol[i];
            for (int q = 0; q < r; q++)
                if ((u >> piv[q]) & 1u) u ^= red[q];
            int hb = 13;
            while (hb > 0 && !((u >> hb) & 1u)) hb--;
            piv[r] = hb; red[r] = u; ispiv[hb] = true; r++;
        }
    }
    const int ndep = isA ? 5 : 9;
    int Pm[9] = {};
    bool used[14] = {};
    for (int b = 0; b < 14; b++) used[b] = ispiv[b];
    if (isA) {
        int idx = 0;
        for (int b = 0; b < 14 && idx < 5; b++)
            if (!used[b]) { Pm[idx++] = b; used[b] = true; }
    } else {
        for (int i = 0; i < 4; i++) { Pm[i] = T.Bqpos[i]; used[T.Bqpos[i]] = true; }
        int idx = 4;
        for (int b = 0; b < 14 && idx < 9; b++)
            if (!used[b]) { Pm[idx++] = b; used[b] = true; }
    }
    M.ndep = ndep;
    for (int i = 0; i < 9; i++) M.Pmv[i] = (i < ndep) ? Pm[i] : 0;
    unsigned freemask = 0;
    for (int i = 0; i < ndep; i++) freemask |= 1u << Pm[i];
    for (int j = 0; j < K; j++)
        M.zflip[j] = ((M.rrow[j] & freemask) == 0u) ? 1 : 0;
    M.ngrp = 0;
    int i2 = 0;
    while (i2 < ndep) {
        int d = Pm[i2] - i2;
        unsigned mm = 0; int j2 = i2;
        while (j2 < ndep && Pm[j2] - j2 == d) { mm |= 1u << j2; j2++; }
        M.gmask[M.ngrp] = mm; M.gshift[M.ngrp] = d; M.ngrp++;
        i2 = j2;
    }
    return M;
}

struct FinC { unsigned m[14]; unsigned rmap[14]; };
__host__ __device__ constexpr FinC build_fin() {
    FinC F = {};
    const MPass M = build_mpass(5);
    for (int w = 0; w < 14; w++) {
        const unsigned r = rowR(3, w);
        unsigned mm = 0;
        for (int j = 0; j < 4; j++)
            if (cpop(M.vcol[j] & r) & 1) mm |= 1u << j;
        F.m[w] = mm;
        unsigned rm = 0;
        for (int i = 0; i < 4; i++) rm |= ((r >> M.Pmv[i]) & 1u) << i;
        rm |= ((unsigned)(cpop(M.vcol[4] & r) & 1)) << 4;
        for (int i = 5; i < 10; i++) rm |= ((r >> M.Pmv[i - 1]) & 1u) << i;
        F.rmap[w] = rm;
    }
    return F;
}

// ============ packed f32x2 helpers ============
__device__ __forceinline__ ull pk2(float lo, float hi) {
    ull r; asm("mov.b64 %0,{%1,%2};" : "=l"(r) : "f"(lo), "f"(hi)); return r;
}
__device__ __forceinline__ void unpk(ull v, float& lo, float& hi) {
    asm("mov.b64 {%0,%1},%2;" : "=f"(lo), "=f"(hi) : "l"(v));
}
__device__ __forceinline__ ull f2(ull a, ull b, ull c) {
    ull d; asm("fma.rn.f32x2 %0,%1,%2,%3;" : "=l"(d) : "l"(a), "l"(b), "l"(c)); return d;
}
__device__ __forceinline__ ull m2(ull a, ull b) {
    ull d; asm("mul.rn.f32x2 %0,%1,%2;" : "=l"(d) : "l"(a), "l"(b)); return d;
}

__device__ __forceinline__ void vbfly(ull& R0, ull& I0, ull& R1, ull& I1,
                                      const ulonglong2* cv)
{
    const ulonglong2 a = cv[0], b = cv[1], c = cv[2], d = cv[3];
    const ull V0 = a.x, N1 = a.y, V2 = b.x, N3 = b.y, V1 = c.x, V3 = c.y, N2 = d.x;
    const ull r0 = R0, i0 = I0, r1 = R1, i1 = I1;
    R0 = f2(V0, r0, f2(N1, i0, f2(V2, r1, m2(N3, i1))));
    I0 = f2(V1, r0, f2(V0, i0, f2(V3, r1, m2(V2, i1))));
    R1 = f2(N2, r0, f2(N3, i0, f2(V0, r1, m2(V1, i1))));
    I1 = f2(V3, r0, f2(N2, i0, f2(N1, r1, m2(V0, i1))));
}
__device__ __forceinline__ void hbfly(ull& R, ull& I, const ulonglong2* ch)
{
    const ulonglong2 a = ch[0], b = ch[1], c = ch[2];
    const ull HA = a.x, HB = a.y, HC = b.x, HD = b.y, HE = c.x, HF = c.y;
    float r0, r1, i0, i1;
    unpk(R, r0, r1); unpk(I, i0, i1);
    const ull B0r = pk2(r0, r0), B0i = pk2(i0, i0);
    const ull B1r = pk2(r1, r1), B1i = pk2(i1, i1);
    R = f2(HA, B0r, f2(HB, B0i, f2(HC, B1r, m2(HD, B1i))));
    I = f2(HE, B0r, f2(HA, B0i, f2(HF, B1r, m2(HC, B1i))));
}

// ============ merged-pass gate engine ============
template<int PI, bool FIRST>
__device__ __forceinline__ void mp_load_gates(
    ull* R, ull* I, unsigned& ydep_out, unsigned& sbase_out,
    float* sRe, float* sIm, const float* __restrict__ gsrc,
    const ulonglong2 (*vu)[4], const ulonglong2 (*hh)[3],
    const ulonglong2* ss, int tid)
{
    constexpr MPass M = build_mpass(PI);
    static_assert(M.ok == 1, "wire partition search failed");
    const int lane = tid & 31;

    unsigned o, laneS = 0, laneR = 0;
    if (M.nsh == 5) {
        o = (unsigned)tid >> 5;
        #pragma unroll
        for (int j = 0; j < 5; j++)
            if ((lane >> j) & 1) { laneS ^= M.lanS[j]; laneR ^= M.lanR[j]; }
    } else {
        o = ((unsigned)tid & 15u) | (((unsigned)tid >> 1) & 0x1F0u);
        if ((lane >> 4) & 1) { laneS = M.lanS[0]; laneR = M.lanR[0]; }
    }
    unsigned ydep = 0;
    #pragma unroll
    for (int g = 0; g < M.ngrp; g++) {
        if (M.gshift[g] >= 0) ydep |= (o & M.gmask[g]) << M.gshift[g];
        else                  ydep |= (o & M.gmask[g]) >> (-M.gshift[g]);
    }
    ydep_out = ydep;
    const unsigned sbase = sig(ydep) ^ laneS;
    sbase_out = sbase;

    if (FIRST) {
        const unsigned yb = ydep ^ laneR;
        #pragma unroll
        for (int m = 0; m < 8; m++) {
            R[m] = pk2(__ldg(gsrc + (yb ^ M.rawc[m])),
                       __ldg(gsrc + (yb ^ M.rawc[m] ^ M.v0raw)));
            I[m] = pk2(0.f, 0.f);
        }
    } else {
        #pragma unroll
        for (int m = 0; m < 8; m++) {
            const unsigned f0 = sbase ^ M.scombo[m], f1 = f0 ^ M.sv0;
            R[m] = pk2(sRe[f0], sRe[f1]);
            I[m] = pk2(sIm[f0], sIm[f1]);
        }
    }

    {   // gate 0: horizontal
        const int fl = M.zflip[0] ? 0 : (__popc(ydep & M.rrow[0]) & 1);
        const ulonglong2* ch = hh[(M.gate[0] << 1) + fl];
        #pragma unroll
        for (int m = 0; m < 8; m++) hbfly(R[m], I[m], ch);
    }
    #pragma unroll
    for (int j = 1; j < 4; j++) {   // gates 1..3: vertical
        const int fl = M.zflip[j] ? 0 : (__popc(ydep & M.rrow[j]) & 1);
        const ulonglong2* cv = vu[(M.gate[j] << 1) + fl];
        const int bb = 1 << (j - 1);
        #pragma unroll
        for (int m = 0; m < 8; m++)
            if (!(m & bb)) vbfly(R[m], I[m], R[m | bb], I[m | bb], cv);
    }
    #pragma unroll
    for (int j = 0; j < M.nsh; j++) {   // shfl gates
        const int gj = 4 + j;
        const int msk  = (M.nsh == 5) ? (1 << j) : 16;
        const int side = (M.nsh == 5) ? ((lane >> j) & 1) : ((lane >> 4) & 1);
        const int fl = M.zflip[gj] ? 0 : (__popc(ydep & M.rrow[gj]) & 1);
        const ulonglong2* cs = ss + (size_t)((M.gate[gj] * 2 + fl) * 2 + side) * 3;
        const ulonglong2 e0 = cs[0], e1 = cs[1], e2 = cs[2];
        #pragma unroll
        for (int m = 0; m < 8; m++) {
            const ull pR = __shfl_xor_sync(0xffffffffu, R[m], msk);
            const ull pI = __shfl_xor_sync(0xffffffffu, I[m], msk);
            const ull oR = R[m], oI = I[m];
            R[m] = f2(e0.x, oR, f2(e0.y, oI, f2(e1.x, pR, m2(e1.y, pI))));
            I[m] = f2(e2.x, oR, f2(e0.x, oI, f2(e2.y, pR, m2(e1.x, pI))));
        }
    }
}

template<int PI, bool FIRST>
__device__ __forceinline__ void do_mpass(float* sRe, float* sIm,
    const float* __restrict__ gsrc,
    const ulonglong2 (*vu)[4], const ulonglong2 (*hh)[3],
    const ulonglong2* ss, int tid)
{
    constexpr MPass M = build_mpass(PI);
    ull R[8], I[8];
    unsigned ydep, sbase;
    mp_load_gates<PI, FIRST>(R, I, ydep, sbase, sRe, sIm, gsrc, vu, hh, ss, tid);
    #pragma unroll
    for (int m = 0; m < 8; m++) {
        const unsigned f0 = sbase ^ M.scombo[m], f1 = f0 ^ M.sv0;
        float x, y;
        unpk(R[m], x, y); sRe[f0] = x; sRe[f1] = y;
        unpk(I[m], x, y); sIm[f0] = x; sIm[f1] = y;
    }
}

__device__ __forceinline__ void do_final(float* sRe, float* sIm,
    const ulonglong2 (*vu)[4], const ulonglong2 (*hh)[3],
    const ulonglong2* ss, int tid, float s_red[][14])
{
    constexpr FinC F = build_fin();
    ull R[8], I[8];
    unsigned ydep, sbase;
    mp_load_gates<5, false>(R, I, ydep, sbase, sRe, sIm, (const float*)0,
                            vu, hh, ss, tid);
    float p[16];
    #pragma unroll
    for (int m = 0; m < 8; m++) {
        const ull pp = f2(R[m], R[m], m2(I[m], I[m]));
        unpk(pp, p[2 * m], p[2 * m + 1]);
    }
    #pragma unroll
    for (int s = 0; s < 4; s++) {
        #pragma unroll
        for (int kk = 0; kk < 16; kk++) {
            if (!((kk >> s) & 1)) {
                const int k1 = kk | (1 << s);
                const float u = p[kk], v = p[k1];
                p[kk] = u + v; p[k1] = u - v;
            }
        }
    }
    const int warp = tid >> 5, lane = tid & 31;
    #pragma unroll
    for (int w = 0; w < 14; w++) {
        float v = p[F.m[w]];
        v = (__popc((unsigned)tid & F.rmap[w]) & 1) ? -v : v;
        #pragma unroll
        for (int off = 16; off; off >>= 1)
            v += __shfl_xor_sync(0xffffffffu, v, off);
        if (lane == 0) s_red[warp][w] = v;
    }
}

// ============ kernel ============
extern __shared__ float s_dyn[];   // sRe[16384] then sIm[16384]

__global__ void __launch_bounds__(NT, 1)
qsim_kernel(const float* __restrict__ state,
            const float* __restrict__ params,
            const float* __restrict__ head_w,
            const float* __restrict__ head_b,
            float* __restrict__ out)
{
    __shared__ ulonglong2 s_vu[84][4];
    __shared__ ulonglong2 s_h[84][3];
    __shared__ ulonglong2 s_ss[168 * 3];
    __shared__ float s_red[NT / 32][14];
    __shared__ float s_feat[14];
    float* sRe = s_dyn;
    float* sIm = s_dyn + QDIM;

    const int tid = threadIdx.x;
    const int b   = blockIdx.x;
    const float* gsrc = state + (size_t)b * QDIM;

    // U = RY(t2)*RX(t1) = [[a,b],[-b*,a*]]; flip: aI->-aI, bR->-bR
    if (tid < 84) {
        const int g = tid >> 1, q = tid & 1;
        const float tx = params[g * 2 + 0] * 0.5f;
        const float ty = params[g * 2 + 1] * 0.5f;
        float s1, c1, s2, c2;
        sincosf(tx, &s1, &c1);
        sincosf(ty, &s2, &c2);
        const float aR = c1 * c2, bI = -c2 * s1;
        float aI = s1 * s2, bR = -s2 * c1;
        if (q) { aI = -aI; bR = -bR; }
        ulonglong2 t;
        t.x = pk2(aR, aR);   t.y = pk2(-aI, -aI); s_vu[tid][0] = t;
        t.x = pk2(bR, bR);   t.y = pk2(-bI, -bI); s_vu[tid][1] = t;
        t.x = pk2(aI, aI);   t.y = pk2(bI, bI);   s_vu[tid][2] = t;
        t.x = pk2(-bR, -bR); t.y = pk2(0.f, 0.f); s_vu[tid][3] = t;
        t.x = pk2(aR, -bR);  t.y = pk2(-aI, -bI); s_h[tid][0] = t;
        t.x = pk2(bR, aR);   t.y = pk2(-bI, aI);  s_h[tid][1] = t;
        t.x = pk2(aI, bI);   t.y = pk2(bI, -aI);  s_h[tid][2] = t;
    }
    if (tid >= 128 && tid < 128 + 168) {
        const int t = tid - 128;
        const int g = t >> 2, fl = (t >> 1) & 1, sd = t & 1;
        const float tx = params[g * 2 + 0] * 0.5f;
        const float ty = params[g * 2 + 1] * 0.5f;
        float s1, c1, s2, c2;
        sincosf(tx, &s1, &c1);
        sincosf(ty, &s2, &c2);
        const float aR = c1 * c2, bI = -c2 * s1;
        float aI = s1 * s2, bR = -s2 * c1;
        if (fl) { aI = -aI; bR = -bR; }
        const float PR = aR, PI = sd ? -aI : aI;
        const float QR = sd ? -bR : bR, QI = bI;
        ulonglong2 u;
        u.x = pk2(PR, PR); u.y = pk2(-PI, -PI); s_ss[t * 3 + 0] = u;
        u.x = pk2(QR, QR); u.y = pk2(-QI, -QI); s_ss[t * 3 + 1] = u;
        u.x = pk2(PI, PI); u.y = pk2(QI, QI);   s_ss[t * 3 + 2] = u;
    }
    __syncthreads();

    do_mpass<0, true >(sRe, sIm, gsrc, s_vu, s_h, s_ss, tid); __syncthreads();
    do_mpass<1, false>(sRe, sIm, gsrc, s_vu, s_h, s_ss, tid); __syncthreads();
    do_mpass<2, false>(sRe, sIm, gsrc, s_vu, s_h, s_ss, tid); __syncthreads();
    do_mpass<3, false>(sRe, sIm, gsrc, s_vu, s_h, s_ss, tid); __syncthreads();
    do_mpass<4, false>(sRe, sIm, gsrc, s_vu, s_h, s_ss, tid); __syncthreads();
    do_final(sRe, sIm, s_vu, s_h, s_ss, tid, s_red);
    __syncthreads();

    if (tid < 14) {
        float f = 0.0f;
        #pragma unroll
        for (int q = 0; q < NT / 32; q++) f += s_red[q][tid];
        s_feat[tid] = f * head_w[tid];
    }
    __syncthreads();
    if (tid == 0) {
        float o = head_b[0];
        #pragma unroll
        for (int w = 0; w < 14; w++) o += s_feat[w];
        out[b] = o;
    }
}

// ============ entry point ============
extern "C" void kernel_launch(void* const* d_in, const int* in_sizes, int n_in,
                              void* d_out, int out_size)
{
    (void)in_sizes; (void)n_in; (void)out_size;
    const float* state  = (const float*)d_in[0];
    const float* params = (const float*)d_in[1];
    const float* head_w = (const float*)d_in[2];
    const float* head_b = (const float*)d_in[3];
    float* out = (float*)d_out;

    const int smem = 2 * QDIM * (int)sizeof(float);   // 128 KB

    static bool attr_done = false;
    if (!attr_done) {
        cudaFuncSetAttribute(qsim_kernel,
                             cudaFuncAttributeMaxDynamicSharedMemorySize, smem);
        attr_done = true;
    }

    qsim_kernel<<<QBATCH, NT, smem>>>(state, params, head_w, head_b, out);
}

// round 17
// speedup vs baseline: 1.5290x; 1.5290x over previous
#include <cuda_runtime.h>
#include <math.h>

#define NW 14
#define QDIM 16384
#define QBATCH 1024
#define NT 512

typedef unsigned long long ull;

// ============ compile-time GF(2) circuit algebra ============
__host__ __device__ constexpr unsigned sig(unsigned y) { return y ^ (y >> 7); }
__host__ __device__ constexpr int cpop(unsigned x) {
    int c = 0; while (x) { c += (int)(x & 1u); x >>= 1; } return c;
}

__host__ __device__ constexpr unsigned hc(unsigned x, int c, int t) {
    int pc = 13 - c, pt = 13 - t;
    return x ^ (((x >> pc) & 1u) << pt);
}
__host__ __device__ constexpr unsigned Gf(unsigned x) {
    x = hc(x, 13, 0);
    for (int w = 12; w >= 0; --w) x = hc(x, w, w + 1);
    return x;
}
__host__ __device__ constexpr unsigned Gi(unsigned x) {
    for (int w = 0; w <= 12; ++w) x = hc(x, w, w + 1);
    x = hc(x, 13, 0);
    return x;
}
__host__ __device__ constexpr unsigned colV(int L, int w) {
    unsigned e = 1u << (13 - w);
    for (int i = 0; i < L; i++) e = Gf(e);
    return e;
}
__host__ __device__ constexpr unsigned rowR(int L, int w) {
    unsigned rr = 0;
    for (int j = 0; j < 14; j++) {
        unsigned e = 1u << j;
        for (int i = 0; i < L; i++) e = Gi(e);
        rr |= ((e >> (13 - w)) & 1u) << j;
    }
    return rr;
}

// ---- pass descriptor: K in {4,5}; layer = [5,5,4]; 9 passes ----
struct PassC {
    unsigned vcol[5], rrow[5];
    int gate[5], zflip[5];
    unsigned rawc[16], scombo[16], v0raw, sv0;
    int K, ndep, ngrp, ok;
    unsigned gmask[12]; int gshift[12];
};

__host__ __device__ constexpr PassC build_pass(int pi) {
    PassC P = {};
    const int L = pi / 3, slot = pi % 3;
    const int K = (slot == 2) ? 4 : 5;
    const int base = slot * 5;          // 0, 5, 10

    for (int j = 0; j < K; j++) {
        P.vcol[j] = colV(L, base + j);
        P.rrow[j] = rowR(L, base + j);
        P.gate[j] = L * 14 + base + j;
    }
    const int NP = 1 << (K - 1);
    for (int m = 0; m < NP; m++) {
        unsigned cb = 0;
        for (int i = 0; i < K - 1; i++)
            if ((m >> i) & 1) cb ^= P.vcol[1 + i];
        P.rawc[m] = cb;
        P.scombo[m] = sig(cb);
    }
    P.v0raw = P.vcol[0];
    P.sv0   = sig(P.vcol[0]);

    // Gaussian elimination over the K columns -> pivot positions
    bool ispiv[14] = {};
    {
        unsigned red[5] = {}; int piv[5] = {}; int r = 0;
        for (int i = 0; i < K; i++) {
            unsigned u = P.vcol[i];
            for (int q = 0; q < r; q++)
                if ((u >> piv[q]) & 1u) u ^= red[q];
            int hb = 13;
            while (hb > 0 && !((u >> hb) & 1u)) hb--;
            piv[r] = hb; red[r] = u; ispiv[hb] = true; r++;
        }
    }

    const int ndep = 14 - K;            // K5: 9 (= tid bits), K4: 10 (tid + loop bit)
    bool used[14] = {};
    for (int b = 0; b < 14; b++) used[b] = ispiv[b];
    bool bankused[5] = {};
    int Pm[12] = {};
    int ok = 1;

    // lane bits 0..4: place at a position whose sigma-bank projection is a fresh bank
    for (int t = 0; t < 5; t++) {
        int pos = -1;
        if (!bankused[t] && !used[t])            { pos = t;     bankused[t] = true; }
        else if (!bankused[t] && !used[t + 7])   { pos = t + 7; bankused[t] = true; }
        else {
            for (int b = 0; b < 5 && pos < 0; b++) {
                if (bankused[b]) continue;
                if (!used[b])          { pos = b;     bankused[b] = true; }
                else if (!used[b + 7]) { pos = b + 7; bankused[b] = true; }
            }
        }
        if (pos < 0) {   // no bank-projecting slot left: take any free (perf fallback)
            for (int b = 0; b < 14 && pos < 0; b++)
                if (!used[b]) pos = b;
            if (pos < 0) ok = 0;
        }
        if (pos >= 0) { Pm[t] = pos; used[pos] = true; }
    }
    for (int i = 5; i < ndep; i++) {
        int pos = -1;
        for (int b = 0; b < 14 && pos < 0; b++)
            if (!used[b]) pos = b;
        if (pos < 0) ok = 0;
        else { Pm[i] = pos; used[pos] = true; }
    }

    unsigned freemask = 0;
    for (int i = 0; i < ndep; i++) freemask |= 1u << Pm[i];
    for (int j = 0; j < K; j++)
        P.zflip[j] = ((P.rrow[j] & freemask) == 0u) ? 1 : 0;
    for (int j = K; j < 5; j++) P.zflip[j] = 1;

    P.K = K; P.ndep = ndep; P.ok = ok; P.ngrp = 0;
    int i2 = 0;
    while (i2 < ndep) {
        int d = Pm[i2] - i2;
        unsigned mm = 0; int j2 = i2;
        while (j2 < ndep && Pm[j2] - j2 == d) { mm |= 1u << j2; j2++; }
        P.gmask[P.ngrp] = mm; P.gshift[P.ngrp] = d; P.ngrp++;
        i2 = j2;
    }
    return P;
}

// measurement WHT index per wire (final pass = pi 8, K=4)
struct FinC { unsigned m[14]; };
__host__ __device__ constexpr FinC build_fin() {
    FinC F = {};
    const PassC P = build_pass(8);
    for (int w = 0; w < 14; w++) {
        const unsigned r = rowR(3, w);
        unsigned mm = 0;
        for (int j = 0; j < 4; j++)
            if (cpop(P.vcol[j] & r) & 1) mm |= 1u << j;
        F.m[w] = mm;
    }
    return F;
}

// ============ packed f32x2 helpers ============
__device__ __forceinline__ ull pk2(float lo, float hi) {
    ull r; asm("mov.b64 %0,{%1,%2};" : "=l"(r) : "f"(lo), "f"(hi)); return r;
}
__device__ __forceinline__ void unpk(ull v, float& lo, float& hi) {
    asm("mov.b64 {%0,%1},%2;" : "=f"(lo), "=f"(hi) : "l"(v));
}
__device__ __forceinline__ ull f2(ull a, ull b, ull c) {
    ull d; asm("fma.rn.f32x2 %0,%1,%2,%3;" : "=l"(d) : "l"(a), "l"(b), "l"(c)); return d;
}
__device__ __forceinline__ ull m2(ull a, ull b) {
    ull d; asm("mul.rn.f32x2 %0,%1,%2;" : "=l"(d) : "l"(a), "l"(b)); return d;
}

// vertical butterfly: two independent complex butterflies, zero swaps
__device__ __forceinline__ void vbfly(ull& R0, ull& I0, ull& R1, ull& I1,
                                      const ulonglong2* cv)
{
    const ulonglong2 a = cv[0], b = cv[1], c = cv[2], d = cv[3];
    const ull V0 = a.x, N1 = a.y, V2 = b.x, N3 = b.y, V1 = c.x, V3 = c.y, N2 = d.x;
    const ull r0 = R0, i0 = I0, r1 = R1, i1 = I1;
    R0 = f2(V0, r0, f2(N1, i0, f2(V2, r1, m2(N3, i1))));
    I0 = f2(V1, r0, f2(V0, i0, f2(V3, r1, m2(V2, i1))));
    R1 = f2(N2, r0, f2(N3, i0, f2(V0, r1, m2(V1, i1))));
    I1 = f2(V3, r0, f2(N2, i0, f2(N1, r1, m2(V0, i1))));
}
// horizontal butterfly: the two lanes ARE the butterfly pair
__device__ __forceinline__ void hbfly(ull& R, ull& I, const ulonglong2* ch)
{
    const ulonglong2 a = ch[0], b = ch[1], c = ch[2];
    const ull HA = a.x, HB = a.y, HC = b.x, HD = b.y, HE = c.x, HF = c.y;
    float r0, r1, i0, i1;
    unpk(R, r0, r1); unpk(I, i0, i1);
    const ull B0r = pk2(r0, r0), B0i = pk2(i0, i0);
    const ull B1r = pk2(r1, r1), B1i = pk2(i1, i1);
    R = f2(HA, B0r, f2(HB, B0i, f2(HC, B1r, m2(HD, B1i))));
    I = f2(HE, B0r, f2(HA, B0i, f2(HF, B1r, m2(HC, B1i))));
}

template<int PI>
__device__ __forceinline__ unsigned orbit_rep(int o) {
    constexpr PassC P = build_pass(PI);
    unsigned yr = 0;
    #pragma unroll
    for (int g = 0; g < P.ngrp; g++) {
        if (P.gshift[g] >= 0) yr |= ((unsigned)o & P.gmask[g]) << P.gshift[g];
        else                  yr |= ((unsigned)o & P.gmask[g]) >> (-P.gshift[g]);
    }
    return yr;
}

// apply the K gates of pass PI on the register orbit
template<int PI, int NP>
__device__ __forceinline__ void apply_pass_gates(ull* R, ull* I, unsigned ydep,
                                                 const ulonglong2 (*vu)[4],
                                                 const ulonglong2 (*hh)[3])
{
    constexpr PassC P = build_pass(PI);
    {   // gate 0: horizontal
        const int fl = P.zflip[0] ? 0 : (__popc(ydep & P.rrow[0]) & 1);
        const ulonglong2* ch = hh[(P.gate[0] << 1) + fl];
        #pragma unroll
        for (int m = 0; m < NP; m++) hbfly(R[m], I[m], ch);
    }
    #pragma unroll
    for (int j = 1; j < P.K; j++) {   // gates 1..K-1: vertical, swap-free
        const int fl = P.zflip[j] ? 0 : (__popc(ydep & P.rrow[j]) & 1);
        const ulonglong2* cv = vu[(P.gate[j] << 1) + fl];
        const int bb = 1 << (j - 1);
        #pragma unroll
        for (int m = 0; m < NP; m++)
            if (!(m & bb)) vbfly(R[m], I[m], R[m | bb], I[m | bb], cv);
    }
}

// body of one pass for a single orbit rep
template<int PI, bool FIRST>
__device__ __forceinline__ void pass_orbit(float* sRe, float* sIm,
                                           const float* __restrict__ gsrc,
                                           const ulonglong2 (*vu)[4],
                                           const ulonglong2 (*hh)[3], int o)
{
    constexpr PassC P = build_pass(PI);
    constexpr int NP = 1 << (P.K - 1);

    const unsigned ydep = orbit_rep<PI>(o);
    const unsigned syr  = sig(ydep);

    ull R[NP], I[NP];
    if (FIRST) {
        #pragma unroll
        for (int m = 0; m < NP; m++) {
            R[m] = pk2(__ldg(gsrc + (ydep ^ P.rawc[m])),
                       __ldg(gsrc + (ydep ^ P.rawc[m] ^ P.v0raw)));
            I[m] = pk2(0.f, 0.f);
        }
    } else {
        #pragma unroll
        for (int m = 0; m < NP; m++) {
            const unsigned f0 = syr ^ P.scombo[m], f1 = f0 ^ P.sv0;
            R[m] = pk2(sRe[f0], sRe[f1]);
            I[m] = pk2(sIm[f0], sIm[f1]);
        }
    }

    apply_pass_gates<PI, NP>(R, I, ydep, vu, hh);

    #pragma unroll
    for (int m = 0; m < NP; m++) {
        const unsigned f0 = syr ^ P.scombo[m], f1 = f0 ^ P.sv0;
        float x, y;
        unpk(R[m], x, y); sRe[f0] = x; sRe[f1] = y;
        unpk(I[m], x, y); sIm[f0] = x; sIm[f1] = y;
    }
}

template<int PI, bool FIRST>
__device__ __forceinline__ void do_pass(float* sRe, float* sIm,
                                        const float* __restrict__ gsrc,
                                        const ulonglong2 (*vu)[4],
                                        const ulonglong2 (*hh)[3], int tid)
{
    constexpr PassC P = build_pass(PI);
    static_assert(P.ok == 1, "pass placement failed");
    constexpr int NORB = 1 << (NW - P.K);

    if (NORB == NT) {
        pass_orbit<PI, FIRST>(sRe, sIm, gsrc, vu, hh, tid);
    } else {
        pass_orbit<PI, FIRST>(sRe, sIm, gsrc, vu, hh, tid);
        pass_orbit<PI, FIRST>(sRe, sIm, gsrc, vu, hh, tid + NT);
    }
}

// ============ final pass (pi=8, K=4, 2 orbits/thread) + fused measurement ============
__device__ __forceinline__ void fin_orbit(float* sRe, float* sIm,
                                          const ulonglong2 (*vu)[4],
                                          const ulonglong2 (*hh)[3],
                                          int o, float* acc)
{
    constexpr PassC P = build_pass(8);
    constexpr FinC F = build_fin();
    constexpr unsigned MEAS[14] = {
        rowR(3, 0),  rowR(3, 1),  rowR(3, 2),  rowR(3, 3),
        rowR(3, 4),  rowR(3, 5),  rowR(3, 6),  rowR(3, 7),
        rowR(3, 8),  rowR(3, 9),  rowR(3, 10), rowR(3, 11),
        rowR(3, 12), rowR(3, 13)
    };

    const unsigned ydep = orbit_rep<8>(o);
    const unsigned syr  = sig(ydep);

    ull R[8], I[8];
    #pragma unroll
    for (int m = 0; m < 8; m++) {
        const unsigned f0 = syr ^ P.scombo[m], f1 = f0 ^ P.sv0;
        R[m] = pk2(sRe[f0], sRe[f1]);
        I[m] = pk2(sIm[f0], sIm[f1]);
    }

    apply_pass_gates<8, 8>(R, I, ydep, vu, hh);

    float p[16];
    #pragma unroll
    for (int m = 0; m < 8; m++) {
        const ull pp = f2(R[m], R[m], m2(I[m], I[m]));
        unpk(pp, p[2 * m], p[2 * m + 1]);
    }
    #pragma unroll
    for (int s = 0; s < 4; s++) {
        #pragma unroll
        for (int kk = 0; kk < 16; kk++) {
            if (!((kk >> s) & 1)) {
                const int k1 = kk | (1 << s);
                const float u = p[kk], v = p[k1];
                p[kk] = u + v; p[k1] = u - v;
            }
        }
    }
    #pragma unroll
    for (int w = 0; w < 14; w++) {
        const float v = p[F.m[w]];
        acc[w] += (__popc(ydep & MEAS[w]) & 1) ? -v : v;
    }
}

__device__ __forceinline__ void do_final(float* sRe, float* sIm,
                                         const ulonglong2 (*vu)[4],
                                         const ulonglong2 (*hh)[3],
                                         int tid, float s_red[][14])
{
    constexpr PassC P = build_pass(8);
    static_assert(P.ok == 1 && P.K == 4, "final pass invalid");

    float acc[14];
    #pragma unroll
    for (int w = 0; w < 14; w++) acc[w] = 0.f;

    fin_orbit(sRe, sIm, vu, hh, tid, acc);
    fin_orbit(sRe, sIm, vu, hh, tid + NT, acc);

    const int warp = tid >> 5, lane = tid & 31;
    #pragma unroll
    for (int w = 0; w < 14; w++) {
        float v = acc[w];
        #pragma unroll
        for (int off = 16; off; off >>= 1)
            v += __shfl_xor_sync(0xffffffffu, v, off);
        if (lane == 0) s_red[warp][w] = v;
    }
}

// ============ kernel ============
extern __shared__ float s_dyn[];   // sRe[16384] then sIm[16384]

__global__ void __launch_bounds__(NT, 1)
qsim_kernel(const float* __restrict__ state,
            const float* __restrict__ params,
            const float* __restrict__ head_w,
            const float* __restrict__ head_b,
            float* __restrict__ out)
{
    __shared__ ulonglong2 s_vu[84][4];
    __shared__ ulonglong2 s_h[84][3];
    __shared__ float s_red[NT / 32][14];
    __shared__ float s_feat[14];
    float* sRe = s_dyn;
    float* sIm = s_dyn + QDIM;

    const int tid = threadIdx.x;
    const int b   = blockIdx.x;
    const float* gsrc = state + (size_t)b * QDIM;

    // U = RY(t2)*RX(t1) = [[a,b],[-b*,a*]]; flip: aI->-aI, bR->-bR
    if (tid < 84) {
        const int g = tid >> 1, q = tid & 1;
        const float tx = params[g * 2 + 0] * 0.5f;
        const float ty = params[g * 2 + 1] * 0.5f;
        float s1, c1, s2, c2;
        sincosf(tx, &s1, &c1);
        sincosf(ty, &s2, &c2);
        const float aR = c1 * c2, bI = -c2 * s1;
        float aI = s1 * s2, bR = -s2 * c1;
        if (q) { aI = -aI; bR = -bR; }
        ulonglong2 t;
        t.x = pk2(aR, aR);   t.y = pk2(-aI, -aI); s_vu[tid][0] = t;
        t.x = pk2(bR, bR);   t.y = pk2(-bI, -bI); s_vu[tid][1] = t;
        t.x = pk2(aI, aI);   t.y = pk2(bI, bI);   s_vu[tid][2] = t;
        t.x = pk2(-bR, -bR); t.y = pk2(0.f, 0.f); s_vu[tid][3] = t;
        t.x = pk2(aR, -bR);  t.y = pk2(-aI, -bI); s_h[tid][0] = t;
        t.x = pk2(bR, aR);   t.y = pk2(-bI, aI);  s_h[tid][1] = t;
        t.x = pk2(aI, bI);   t.y = pk2(bI, -aI);  s_h[tid][2] = t;
    }
    __syncthreads();

    // 9 passes: layer = [K5, K5, K4]; pass 0 reads global; pass 8 fuses measurement
    do_pass<0, true >(sRe, sIm, gsrc, s_vu, s_h, tid); __syncthreads();
    do_pass<1, false>(sRe, sIm, gsrc, s_vu, s_h, tid); __syncthreads();
    do_pass<2, false>(sRe, sIm, gsrc, s_vu, s_h, tid); __syncthreads();
    do_pass<3, false>(sRe, sIm, gsrc, s_vu, s_h, tid); __syncthreads();
    do_pass<4, false>(sRe, sIm, gsrc, s_vu, s_h, tid); __syncthreads();
    do_pass<5, false>(sRe, sIm, gsrc, s_vu, s_h, tid); __syncthreads();
    do_pass<6, false>(sRe, sIm, gsrc, s_vu, s_h, tid); __syncthreads();
    do_pass<7, false>(sRe, sIm, gsrc, s_vu, s_h, tid); __syncthreads();
    do_final(sRe, sIm, s_vu, s_h, tid, s_red);
    __syncthreads();

    if (tid < 14) {
        float f = 0.0f;
        #pragma unroll
        for (int q = 0; q < NT / 32; q++) f += s_red[q][tid];
        s_feat[tid] = f * head_w[tid];
    }
    __syncthreads();
    if (tid == 0) {
        float o = head_b[0];
        #pragma unroll
        for (int w = 0; w < 14; w++) o += s_feat[w];
        out[b] = o;
    }
}

// ============ entry point ============
extern "C" void kernel_launch(void* const* d_in, const int* in_sizes, int n_in,
                              void* d_out, int out_size)
{
    (void)in_sizes; (void)n_in; (void)out_size;
    const float* state  = (const float*)d_in[0];
    const float* params = (const float*)d_in[1];
    const float* head_w = (const float*)d_in[2];
    const float* head_b = (const float*)d_in[3];
    float* out = (float*)d_out;

    const int smem = 2 * QDIM * (int)sizeof(float);   // 128 KB

    static bool attr_done = false;
    if (!attr_done) {
        cudaFuncSetAttribute(qsim_kernel,
                             cudaFuncAttributeMaxDynamicSharedMemorySize, smem);
        attr_done = true;
    }

    qsim_kernel<<<QBATCH, NT, smem>>>(state, params, head_w, head_b, out);
}